// round 17
// baseline (speedup 1.0000x reference)
#include <cuda_runtime.h>
#include <cuda_fp16.h>
#include <cstdint>

// Problem constants
#define NB   16
#define CC   128
#define HH   112
#define WW   112
#define PLANE (HH*WW)          // 12544 pixels per plane
#define PTS   (98*16*16)       // 25088 sample points per image
#define THREADS 512
#define QUAD_ITERS 12          // 12*512 quads; tail = 128 quads (6272 total)
#define TAIL_QUADS 128

static __device__ __forceinline__ unsigned int h2_bits(__half2 h)
{
    union { __half2 h; unsigned int u; } cvt;
    cvt.h = h;
    return cvt.u;
}

static __device__ __forceinline__ __half2 bilerp_h2(const __half2* __restrict__ s,
                                                    float gx, float gy)
{
    const float x = fminf(fmaxf(fmaf(gx + 1.0f, 56.0f, -0.5f), 0.0f), 111.0f);
    const float y = fminf(fmaxf(fmaf(gy + 1.0f, 56.0f, -0.5f), 0.0f), 111.0f);
    const int x0 = min((int)x, WW - 2);
    const int y0 = min((int)y, HH - 2);
    const float wx = x - (float)x0;
    const float wy = y - (float)y0;
    const int b00 = y0 * WW + x0;

    const __half2 q00 = s[b00];
    const __half2 q01 = s[b00 + 1];
    const __half2 q10 = s[b00 + WW];
    const __half2 q11 = s[b00 + WW + 1];

    const __half2 wx2 = __float2half2_rn(wx);
    const __half2 wy2 = __float2half2_rn(wy);
    const __half2 top = __hfma2(wx2, __hsub2(q01, q00), q00);
    const __half2 bot = __hfma2(wx2, __hsub2(q11, q10), q10);
    return __hfma2(wy2, __hsub2(bot, top), top);
}

// smem: one half2 per pixel packing channels (c0, c0+1) -> 50,176 B
__global__ __launch_bounds__(THREADS, 3)
void patches_kernel(const float* __restrict__ fm,
                    const float* __restrict__ grid,
                    float* __restrict__ out)
{
    extern __shared__ __half2 s[];   // PLANE half2

    const int n  = blockIdx.x >> 6;          // 16 images
    const int c0 = (blockIdx.x & 63) * 2;    // 64 channel pairs

    // ---- Stage 2 channel planes packed as half2 (LDG.128 x2 + STS.128) ----
    {
        const float4* __restrict__ pa =
            reinterpret_cast<const float4*>(fm + ((size_t)n * CC + c0) * PLANE);
        const float4* __restrict__ pb = pa + PLANE / 4;
        uint4* __restrict__ sd = reinterpret_cast<uint4*>(s);
        #pragma unroll
        for (int i = threadIdx.x; i < PLANE / 4; i += THREADS) {
            const float4 a = pa[i];
            const float4 b = pb[i];
            uint4 v;
            v.x = h2_bits(__floats2half2_rn(a.x, b.x));
            v.y = h2_bits(__floats2half2_rn(a.y, b.y));
            v.z = h2_bits(__floats2half2_rn(a.z, b.z));
            v.w = h2_bits(__floats2half2_rn(a.w, b.w));
            sd[i] = v;
        }
    }
    __syncthreads();

    const int t = threadIdx.x;

    // Quad of points 4q..4q+3 per thread per iteration (q = i*512 + t).
    // grid: two float4 per quad.
    const float4* __restrict__ g4 =
        reinterpret_cast<const float4*>(grid) + (size_t)n * (PTS / 2) + 2 * t;

    // out[n, p, c, hg, wg]  flat = ((n*98 + p)*128 + c)*256 + pix
    // q = i*512 + t -> p = 8i + (t>>6), pix = (4t)&255
    float* __restrict__ ob = out + (((size_t)n * 98) * CC + c0) * 256;
    float* __restrict__ o = ob + (t >> 6) * (CC * 256) + ((4 * t) & 255);

    #pragma unroll 3
    for (int i = 0; i < QUAD_ITERS; i++) {
        const float4 xyA = g4[i * (2 * THREADS)];      // points 4q, 4q+1
        const float4 xyB = g4[i * (2 * THREADS) + 1];  // points 4q+2, 4q+3

        const __half2 r0 = bilerp_h2(s, xyA.x, xyA.y);
        const __half2 r1 = bilerp_h2(s, xyA.z, xyA.w);
        const __half2 r2 = bilerp_h2(s, xyB.x, xyB.y);
        const __half2 r3 = bilerp_h2(s, xyB.z, xyB.w);

        const float2 f0 = __half22float2(r0);
        const float2 f1 = __half22float2(r1);
        const float2 f2 = __half22float2(r2);
        const float2 f3 = __half22float2(r3);

        // each iteration advances p by 512/64 = 8 rows of [C,256]
        float* __restrict__ oi = o + i * (8 * CC * 256);
        *reinterpret_cast<float4*>(oi)       = make_float4(f0.x, f1.x, f2.x, f3.x);
        *reinterpret_cast<float4*>(oi + 256) = make_float4(f0.y, f1.y, f2.y, f3.y);
    }

    // Tail: 128 quads, q = 6144 + t (t < 128)
    if (t < TAIL_QUADS) {
        const float4 xyA = g4[QUAD_ITERS * (2 * THREADS)];
        const float4 xyB = g4[QUAD_ITERS * (2 * THREADS) + 1];

        const __half2 r0 = bilerp_h2(s, xyA.x, xyA.y);
        const __half2 r1 = bilerp_h2(s, xyA.z, xyA.w);
        const __half2 r2 = bilerp_h2(s, xyB.x, xyB.y);
        const __half2 r3 = bilerp_h2(s, xyB.z, xyB.w);

        const float2 f0 = __half22float2(r0);
        const float2 f1 = __half22float2(r1);
        const float2 f2 = __half22float2(r2);
        const float2 f3 = __half22float2(r3);

        // p = 96 + (t>>6), pix = (4t)&255
        float* __restrict__ ot = ob + (96 + (t >> 6)) * (CC * 256) + ((4 * t) & 255);
        *reinterpret_cast<float4*>(ot)       = make_float4(f0.x, f1.x, f2.x, f3.x);
        *reinterpret_cast<float4*>(ot + 256) = make_float4(f0.y, f1.y, f2.y, f3.y);
    }
}

extern "C" void kernel_launch(void* const* d_in, const int* in_sizes, int n_in,
                              void* d_out, int out_size)
{
    const float* fm   = (const float*)d_in[0];   // [16,128,112,112] f32
    const float* grid = (const float*)d_in[1];   // [16,98,16,16,2]  f32
    float* out        = (float*)d_out;           // [16,98,128,16,16] f32

    const int smem = PLANE * sizeof(__half2);    // 50,176 B
    cudaFuncSetAttribute(patches_kernel,
                         cudaFuncAttributeMaxDynamicSharedMemorySize, smem);

    const int blocks = NB * (CC / 2);            // 1024
    patches_kernel<<<blocks, THREADS, smem>>>(fm, grid, out);
}